// round 1
// baseline (speedup 1.0000x reference)
#include <cuda_runtime.h>
#include <math.h>

#define BB 16
#define NN 1024
#define KK 16
#define EE 4
#define D0 128
#define HH 256
#define PP 10

// Scratch (device globals — allocation-free rule)
__device__ float g_state[BB*NN*HH];        // 16 MB, node states (row stride HH)
__device__ float g_msg[BB*NN*EE*HH];       // 64 MB, aggregated messages
__device__ float g_hid[BB*NN*HH];          // 16 MB, pre-norm hidden
__device__ float g_pool[BB*8*PP];          // pooling partials

typedef unsigned long long u64;

__device__ __forceinline__ void ffma2(u64 &d, u64 a, u64 b){
    asm("fma.rn.f32x2 %0, %1, %2, %0;" : "+l"(d) : "l"(a), "l"(b));
}
__device__ __forceinline__ u64 pack2(float x, float y){
    u64 r; asm("mov.b64 %0, {%1, %2};" : "=l"(r) : "f"(x), "f"(y)); return r;
}
__device__ __forceinline__ void unpack2(u64 v, float &x, float &y){
    asm("mov.b64 {%0, %1}, %2;" : "=f"(x), "=f"(y) : "l"(v));
}

// ---------------------------------------------------------------------------
// 1) Embedding lookup: state[b,n,0:128] = emb[node_feat[b,n], :]
// ---------------------------------------------------------------------------
__global__ void embed_k(const int* __restrict__ nf, const float* __restrict__ emb){
    int i  = blockIdx.x*blockDim.x + threadIdx.x;   // over B*N*D0
    int d  = i & (D0-1);
    int bn = i >> 7;
    g_state[(size_t)bn*HH + d] = emb[nf[bn]*D0 + d];
}

// ---------------------------------------------------------------------------
// 2) Aggregation: msg[b,n,e*D+d] = mask * (1/K) * sum_k state[b, idx[b,n,k,e], d]
//    One block per (batch, 32-column slice). The 1024x32 state slice (128KB)
//    is staged in SMEM so the 1.6 GB of random gathers hit the SMEM crossbar.
// ---------------------------------------------------------------------------
__global__ void agg_k(const float* __restrict__ S, const int* __restrict__ nn_idx,
                      const float* __restrict__ mask, float* __restrict__ msg,
                      int D, int dstStride){
    extern __shared__ float sbuf[];                 // [1024][32]
    int b  = blockIdx.x;
    int d0 = blockIdx.y * 32;
    int tid = threadIdx.x, lane = tid & 31, w = tid >> 5;

    const float* Sb = S + (size_t)b*NN*HH;
    for (int i = tid; i < NN*32; i += 256){
        int row = i >> 5, c = i & 31;
        sbuf[i] = Sb[(size_t)row*HH + d0 + c];      // coalesced 128B per warp
    }
    __syncthreads();

    for (int n = w; n < NN; n += 8){
        const int* ip = nn_idx + ((size_t)(b*NN + n))*(KK*EE);
        int i0 = ip[lane];
        int i1 = ip[32 + lane];
        float m = mask[b*NN + n] * (1.0f/KK);
        float* op = msg + (size_t)(b*NN + n)*dstStride + d0 + lane;
        #pragma unroll
        for (int e = 0; e < EE; e++){
            float acc = 0.f;
            #pragma unroll
            for (int k = 0; k < KK; k++){
                int kk = k*EE + e;
                int idx = (kk < 32) ? __shfl_sync(0xffffffffu, i0, kk)
                                    : __shfl_sync(0xffffffffu, i1, kk - 32);
                acc += sbuf[idx*32 + lane];          // conflict-free: bank == lane
            }
            op[e*D] = acc * m;
        }
    }
}

// ---------------------------------------------------------------------------
// 3) GEMM + bias + ReLU:  C[m,j] = relu(sum_i A[m,i]*W[i,j] + bias[j])
//    128x128x16 tile, 256 threads, 8x8 microtile with f32x2 packed FMA
//    (columns paired). C row stride = HH.
// ---------------------------------------------------------------------------
__global__ __launch_bounds__(256) void gemm_relu_k(
        const float* __restrict__ A, int lda, int Kd,
        const float* __restrict__ Wm, const float* __restrict__ bias,
        float* __restrict__ C){
    __shared__ float As[16][130];   // transposed A tile, pad 130 (even, kills STS conflicts)
    __shared__ float Bs[16][128];
    int m0 = blockIdx.x*128, j0 = blockIdx.y*128;
    int tid = threadIdx.x, tx = tid & 15, ty = tid >> 4;

    u64 acc[8][4];
    #pragma unroll
    for (int r = 0; r < 8; r++)
        #pragma unroll
        for (int j = 0; j < 4; j++) acc[r][j] = 0ull;

    for (int kt = 0; kt < Kd; kt += 16){
        #pragma unroll
        for (int r = 0; r < 2; r++){                 // A tile: 512 float4
            int q = tid + 256*r;
            int row = q >> 2, kq = (q & 3) << 2;
            float4 v = *(const float4*)(A + (size_t)(m0+row)*lda + kt + kq);
            As[kq+0][row] = v.x; As[kq+1][row] = v.y;
            As[kq+2][row] = v.z; As[kq+3][row] = v.w;
        }
        #pragma unroll
        for (int r = 0; r < 2; r++){                 // B tile: 512 float4
            int q = tid + 256*r;
            int k = q >> 5, j4 = (q & 31) << 2;
            *(float4*)&Bs[k][j4] = *(const float4*)(Wm + (size_t)(kt+k)*HH + j0 + j4);
        }
        __syncthreads();
        #pragma unroll
        for (int k = 0; k < 16; k++){
            float2 a2[4]; u64 b2[4]; u64 aa[8];
            #pragma unroll
            for (int i = 0; i < 4; i++) a2[i] = *(const float2*)&As[k][32*i + 2*ty];
            #pragma unroll
            for (int j = 0; j < 4; j++) b2[j] = *(const u64*)&Bs[k][32*j + 2*tx];
            #pragma unroll
            for (int i = 0; i < 4; i++){
                aa[2*i+0] = pack2(a2[i].x, a2[i].x);
                aa[2*i+1] = pack2(a2[i].y, a2[i].y);
            }
            #pragma unroll
            for (int r = 0; r < 8; r++)
                #pragma unroll
                for (int j = 0; j < 4; j++) ffma2(acc[r][j], aa[r], b2[j]);
        }
        __syncthreads();
    }
    // epilogue: bias + relu, write C
    #pragma unroll
    for (int i = 0; i < 4; i++){
        #pragma unroll
        for (int p = 0; p < 2; p++){
            int r = 2*i + p;
            int m = m0 + 32*i + 2*ty + p;
            #pragma unroll
            for (int j = 0; j < 4; j++){
                int c = j0 + 32*j + 2*tx;
                float v0, v1; unpack2(acc[r][j], v0, v1);
                v0 = fmaxf(v0 + bias[c],   0.f);
                v1 = fmaxf(v1 + bias[c+1], 0.f);
                *(float2*)&C[(size_t)m*HH + c] = make_float2(v0, v1);
            }
        }
    }
}

// ---------------------------------------------------------------------------
// 4) Row L2-normalize: state = h / (||h|| + EPS).  One warp per node.
// ---------------------------------------------------------------------------
__global__ void norm_k(const float* __restrict__ Hd, float* __restrict__ S){
    int node = (blockIdx.x*blockDim.x + threadIdx.x) >> 5;
    int lane = threadIdx.x & 31;
    const float* hp = Hd + (size_t)node*HH;
    float v[8]; float ss = 0.f;
    #pragma unroll
    for (int j = 0; j < 8; j++){ v[j] = hp[lane + 32*j]; ss += v[j]*v[j]; }
    #pragma unroll
    for (int off = 16; off; off >>= 1) ss += __shfl_xor_sync(0xffffffffu, ss, off);
    float inv = 1.0f/(sqrtf(ss) + 1.1920928955078125e-07f);
    float* sp = S + (size_t)node*HH;
    #pragma unroll
    for (int j = 0; j < 8; j++) sp[lane + 32*j] = v[j]*inv;
}

// ---------------------------------------------------------------------------
// 5) Output head: per node y = s@Wout+bout, att = sigmoid(s@Watt+batt),
//    partial-pool att*y over nodes. Grid (B, 8); deterministic 2-stage reduce.
// ---------------------------------------------------------------------------
__global__ void final_k(const float* __restrict__ S,
                        const float* __restrict__ Wout, const float* __restrict__ bout,
                        const float* __restrict__ Watt, const float* __restrict__ batt){
    __shared__ float wt[PP*HH];      // Wout transposed: wt[p*HH + d]
    __shared__ float wa[HH];
    __shared__ float red[8][PP];
    int b = blockIdx.x, seg = blockIdx.y;
    int tid = threadIdx.x, lane = tid & 31, w = tid >> 5;

    for (int i = tid; i < PP*HH; i += 256){
        int d = i / PP, p = i - d*PP;
        wt[p*HH + d] = Wout[i];
    }
    if (tid < HH) wa[tid] = Watt[tid];
    __syncthreads();

    float accp = 0.f;
    float ba = batt[0];
    for (int t = 0; t < 16; t++){
        int n = seg*128 + w*16 + t;
        const float* sp = S + (size_t)(b*NN + n)*HH;
        float s[8], att = 0.f, y[PP];
        #pragma unroll
        for (int p = 0; p < PP; p++) y[p] = 0.f;
        #pragma unroll
        for (int j = 0; j < 8; j++){
            s[j] = sp[lane + 32*j];
            att += s[j]*wa[lane + 32*j];
        }
        #pragma unroll
        for (int p = 0; p < PP; p++)
            #pragma unroll
            for (int j = 0; j < 8; j++) y[p] += s[j]*wt[p*HH + lane + 32*j];
        #pragma unroll
        for (int off = 16; off; off >>= 1){
            att += __shfl_xor_sync(0xffffffffu, att, off);
            #pragma unroll
            for (int p = 0; p < PP; p++) y[p] += __shfl_xor_sync(0xffffffffu, y[p], off);
        }
        float a = 1.0f/(1.0f + expf(-(att + ba)));
        if (lane < PP) accp += a * (y[lane] + bout[lane]);
    }
    if (lane < PP) red[w][lane] = accp;
    __syncthreads();
    if (tid < PP){
        float sum = 0.f;
        #pragma unroll
        for (int w2 = 0; w2 < 8; w2++) sum += red[w2][tid];
        g_pool[(b*8 + seg)*PP + tid] = sum;
    }
}

__global__ void reduce_k(float* __restrict__ out){
    int i = threadIdx.x;
    if (i < BB*PP){
        int b = i / PP, p = i - b*PP;
        float s = 0.f;
        #pragma unroll
        for (int seg = 0; seg < 8; seg++) s += g_pool[(b*8 + seg)*PP + p];
        out[i] = s * (1.0f/NN);
    }
}

// ---------------------------------------------------------------------------
extern "C" void kernel_launch(void* const* d_in, const int* in_sizes, int n_in,
                              void* d_out, int out_size){
    (void)in_sizes; (void)n_in; (void)out_size;
    const int*   nf   = (const int*)  d_in[0];
    const int*   nn   = (const int*)  d_in[1];
    const float* mask = (const float*)d_in[2];
    const float* emb  = (const float*)d_in[3];
    const float* W0   = (const float*)d_in[4];
    const float* b0   = (const float*)d_in[5];
    const float* W1   = (const float*)d_in[6];
    const float* b1   = (const float*)d_in[7];
    const float* Wout = (const float*)d_in[8];
    const float* bout = (const float*)d_in[9];
    const float* Watt = (const float*)d_in[10];
    const float* batt = (const float*)d_in[11];
    float* out = (float*)d_out;

    float *state, *msg, *hid;
    cudaGetSymbolAddress((void**)&state, g_state);
    cudaGetSymbolAddress((void**)&msg,   g_msg);
    cudaGetSymbolAddress((void**)&hid,   g_hid);

    cudaFuncSetAttribute(agg_k, cudaFuncAttributeMaxDynamicSharedMemorySize, 131072);

    embed_k<<<BB*NN*D0/256, 256>>>(nf, emb);

    // Layer 0
    agg_k<<<dim3(BB, D0/32), 256, 131072>>>(state, nn, mask, msg, D0, EE*D0);
    gemm_relu_k<<<dim3(BB*NN/128, HH/128), 256>>>(msg, EE*D0, EE*D0, W0, b0, hid);
    norm_k<<<BB*NN/8, 256>>>(hid, state);

    // Layer 1
    agg_k<<<dim3(BB, HH/32), 256, 131072>>>(state, nn, mask, msg, HH, EE*HH);
    gemm_relu_k<<<dim3(BB*NN/128, HH/128), 256>>>(msg, EE*HH, EE*HH, W1, b1, hid);
    norm_k<<<BB*NN/8, 256>>>(hid, state);

    // Output head + pooling
    final_k<<<dim3(BB, 8), 256>>>(state, Wout, bout, Watt, batt);
    reduce_k<<<1, 192>>>(out);
}

// round 3
// speedup vs baseline: 1.4015x; 1.4015x over previous
#include <cuda_runtime.h>
#include <cuda_bf16.h>
#include <math.h>
#include <stdint.h>

#define BB 16
#define NN 1024
#define KK 16
#define EE 4
#define D0 128
#define HH 256
#define PP 10
#define EPSF 1.1920928955078125e-07f

// ---------------- device scratch (allocation-free rule) --------------------
__device__ float          g_state[BB*NN*HH];            // node states (stride HH)
__device__ __nv_bfloat16  g_msg_hi[BB*NN*EE*HH];        // aggregated msg (hi)
__device__ __nv_bfloat16  g_msg_lo[BB*NN*EE*HH];        // aggregated msg (lo)
__device__ __nv_bfloat16  g_wthi[HH*EE*HH];             // Wt[n][k] hi
__device__ __nv_bfloat16  g_wtlo[HH*EE*HH];             // Wt[n][k] lo
__device__ float          g_pool[BB*8*PP];

// ---------------- portable PTX helpers (sm_80-level, safe on compute_103) --
__device__ __forceinline__ uint32_t smem_u32(const void* p){
    uint32_t a; asm("{ .reg .u64 t; cvta.to.shared.u64 t, %1; cvt.u32.u64 %0, t; }" : "=r"(a) : "l"(p));
    return a;
}
__device__ __forceinline__ void cp16(uint32_t dst, const void* src){
    asm volatile("cp.async.cg.shared.global [%0], [%1], 16;" :: "r"(dst), "l"(src));
}
#define CP_COMMIT() asm volatile("cp.async.commit_group;" ::: "memory")
#define CP_WAIT(n)  asm volatile("cp.async.wait_group %0;" :: "n"(n) : "memory")

#define LDMX4(r, a) \
    asm volatile("ldmatrix.sync.aligned.m8n8.x4.shared.b16 {%0,%1,%2,%3}, [%4];" \
        : "=r"((r)[0]), "=r"((r)[1]), "=r"((r)[2]), "=r"((r)[3]) : "r"(a))

__device__ __forceinline__ void mma16816(float* c, const uint32_t* a, uint32_t b0, uint32_t b1){
    asm volatile("mma.sync.aligned.m16n8k16.row.col.f32.bf16.bf16.f32 "
        "{%0,%1,%2,%3}, {%4,%5,%6,%7}, {%8,%9}, {%0,%1,%2,%3};"
        : "+f"(c[0]), "+f"(c[1]), "+f"(c[2]), "+f"(c[3])
        : "r"(a[0]), "r"(a[1]), "r"(a[2]), "r"(a[3]), "r"(b0), "r"(b1));
}

// 64B-row XOR swizzle: 16B chunk g gets g ^ ((row>>1)&3) -> conflict-free ldmatrix
#define SW64(row, g) ((row)*64 + ((unsigned)((g) ^ (((row)>>1)&3)) << 4))

// ---------------------------------------------------------------------------
// 1) Embedding lookup
// ---------------------------------------------------------------------------
__global__ void embed_k(const int* __restrict__ nf, const float* __restrict__ emb){
    int i  = blockIdx.x*blockDim.x + threadIdx.x;
    int d  = i & (D0-1);
    int bn = i >> 7;
    g_state[(size_t)bn*HH + d] = emb[nf[bn]*D0 + d];
}

// ---------------------------------------------------------------------------
// 2) Aggregation -> bf16 hi/lo message buffers (SMEM-staged gather)
// ---------------------------------------------------------------------------
__global__ void agg_k(const float* __restrict__ S, const int* __restrict__ nn_idx,
                      const float* __restrict__ mask, int D, int Kd){
    extern __shared__ float sbuf[];                 // [1024][32]
    int b  = blockIdx.x;
    int d0 = blockIdx.y * 32;
    int tid = threadIdx.x, lane = tid & 31, w = tid >> 5;

    const float* Sb = S + (size_t)b*NN*HH;
    for (int i = tid; i < NN*32; i += 256){
        int row = i >> 5, c = i & 31;
        sbuf[i] = Sb[(size_t)row*HH + d0 + c];
    }
    __syncthreads();

    for (int n = w; n < NN; n += 8){
        const int* ip = nn_idx + ((size_t)(b*NN + n))*(KK*EE);
        int i0 = ip[lane];
        int i1 = ip[32 + lane];
        float m = mask[b*NN + n] * (1.0f/KK);
        size_t base = (size_t)(b*NN + n)*Kd + d0 + lane;
        #pragma unroll
        for (int e = 0; e < EE; e++){
            float acc = 0.f;
            #pragma unroll
            for (int k = 0; k < KK; k++){
                int kk = k*EE + e;
                int idx = (kk < 32) ? __shfl_sync(0xffffffffu, i0, kk)
                                    : __shfl_sync(0xffffffffu, i1, kk - 32);
                acc += sbuf[idx*32 + lane];
            }
            float v = acc * m;
            __nv_bfloat16 h = __float2bfloat16(v);
            __nv_bfloat16 l = __float2bfloat16(v - __bfloat162float(h));
            g_msg_hi[base + (size_t)e*D] = h;
            g_msg_lo[base + (size_t)e*D] = l;
        }
    }
}

// ---------------------------------------------------------------------------
// 3) Weight transpose + bf16 split: Wt[n, k] = W[k, n]
// ---------------------------------------------------------------------------
__global__ void convw_k(const float* __restrict__ W, int Kd){
    int i = blockIdx.x*256 + threadIdx.x;
    if (i < Kd*HH){
        int k = i >> 8, n = i & (HH-1);
        float v = W[(size_t)k*HH + n];
        __nv_bfloat16 h = __float2bfloat16(v);
        g_wthi[(size_t)n*Kd + k] = h;
        g_wtlo[(size_t)n*Kd + k] = __float2bfloat16(v - __bfloat162float(h));
    }
}

// ---------------------------------------------------------------------------
// 4) mma.sync bf16 GEMM (3-term compensated) + bias + ReLU + fused L2-norm.
//    CTA tile 128x256, warp tile 64x64 (8 warps: wm in {0,1}, wn in {0..3}),
//    K-chunk 32, 2-stage cp.async pipeline, swizzled 64B rows.
//    Stage layout: Ah@0 (8KB) Al@8192 Bh@16384 (16KB) Bl@32768 -> 49152/stage.
//    Epilogue reuses smem as float[128][258].
// ---------------------------------------------------------------------------
#define STG_AL 8192
#define STG_B  16384
#define STG_BL 32768
#define STAGE_SZ 49152
#define EPI_STR 258
#define GEMM_SMEM 132096

__global__ __launch_bounds__(256, 1) void gemm_mma_k(
        const __nv_bfloat16* __restrict__ Ahi, const __nv_bfloat16* __restrict__ Alo,
        int Kd, const float* __restrict__ bias, float* __restrict__ S){
    extern __shared__ char smx[];
    uint32_t sb0 = smem_u32(smx);
    int tid = threadIdx.x, lane = tid & 31, w = tid >> 5;
    int wm = w >> 2, wn = w & 3;
    int m0 = blockIdx.x * 128;

    const __nv_bfloat16* Bhi = g_wthi;
    const __nv_bfloat16* Blo = g_wtlo;

    float c[4][8][4];
    #pragma unroll
    for (int mi = 0; mi < 4; mi++)
        #pragma unroll
        for (int nj = 0; nj < 8; nj++)
            #pragma unroll
            for (int q = 0; q < 4; q++) c[mi][nj][q] = 0.f;

    const int nch = Kd >> 5;

    // --- cp.async tile issue ---
    auto issue = [&](int ch){
        uint32_t sb = sb0 + (ch & 1)*STAGE_SZ;
        int c0 = ch << 5;
        #pragma unroll
        for (int i = 0; i < 2; i++){                 // A: 512 uint4
            int idx = tid + i*256;
            int row = idx >> 2, g = idx & 3;
            uint32_t d = sb + SW64(row, g);
            const __nv_bfloat16* sa = Ahi + (size_t)(m0+row)*Kd + c0 + g*8;
            cp16(d, sa);
            cp16(d + STG_AL, Alo + (size_t)(m0+row)*Kd + c0 + g*8);
        }
        #pragma unroll
        for (int i = 0; i < 4; i++){                 // B: 1024 uint4
            int idx = tid + i*256;
            int row = idx >> 2, g = idx & 3;
            uint32_t d = sb + STG_B + SW64(row, g);
            cp16(d,           Bhi + (size_t)row*Kd + c0 + g*8);
            cp16(d + 16384,   Blo + (size_t)row*Kd + c0 + g*8);
        }
        CP_COMMIT();
    };

    issue(0);
    for (int ch = 0; ch < nch; ch++){
        if (ch + 1 < nch){ issue(ch + 1); CP_WAIT(1); }
        else             { CP_WAIT(0); }
        __syncthreads();

        uint32_t sb = sb0 + (ch & 1)*STAGE_SZ;
        #pragma unroll
        for (int pass = 0; pass < 3; pass++){
            uint32_t abase = sb + (pass == 2 ? STG_AL : 0);
            uint32_t bbase = sb + (pass == 1 ? STG_BL : STG_B);
            #pragma unroll
            for (int s = 0; s < 2; s++){
                uint32_t a[4][4], bq[4][4];
                int lrow = lane & 15;
                int g = 2*s + (lane >> 4);
                #pragma unroll
                for (int mi = 0; mi < 4; mi++){
                    int row = wm*64 + mi*16 + lrow;
                    LDMX4(a[mi], abase + SW64(row, g));
                }
                #pragma unroll
                for (int nj = 0; nj < 4; nj++){
                    int row = wn*64 + nj*16 + lrow;
                    LDMX4(bq[nj], bbase + SW64(row, g));
                }
                #pragma unroll
                for (int mi = 0; mi < 4; mi++)
                    #pragma unroll
                    for (int nj = 0; nj < 4; nj++){
                        mma16816(c[mi][2*nj+0], a[mi], bq[nj][0], bq[nj][2]);
                        mma16816(c[mi][2*nj+1], a[mi], bq[nj][1], bq[nj][3]);
                    }
            }
        }
        __syncthreads();
    }

    // --- epilogue: bias + relu into smem, then fused row L2-norm ---
    float* sbuf = (float*)smx;
    int qr = lane >> 2, qc = (lane & 3)*2;
    #pragma unroll
    for (int mi = 0; mi < 4; mi++){
        int r0 = wm*64 + mi*16 + qr;
        #pragma unroll
        for (int nj = 0; nj < 8; nj++){
            int col = wn*64 + nj*8 + qc;
            float b0 = bias[col], b1 = bias[col+1];
            float2 v0 = make_float2(fmaxf(c[mi][nj][0] + b0, 0.f),
                                    fmaxf(c[mi][nj][1] + b1, 0.f));
            float2 v1 = make_float2(fmaxf(c[mi][nj][2] + b0, 0.f),
                                    fmaxf(c[mi][nj][3] + b1, 0.f));
            *(float2*)&sbuf[(size_t)r0*EPI_STR + col]       = v0;
            *(float2*)&sbuf[(size_t)(r0+8)*EPI_STR + col]   = v1;
        }
    }
    __syncthreads();

    #pragma unroll
    for (int r = 0; r < 16; r++){
        int row = w*16 + r;
        const float* rp = &sbuf[(size_t)row*EPI_STR];
        float v[8], ss = 0.f;
        #pragma unroll
        for (int j = 0; j < 8; j++){ v[j] = rp[lane + 32*j]; ss += v[j]*v[j]; }
        #pragma unroll
        for (int off = 16; off; off >>= 1) ss += __shfl_xor_sync(0xffffffffu, ss, off);
        float inv = 1.0f/(sqrtf(ss) + EPSF);
        float* op = S + (size_t)(m0 + row)*HH;
        #pragma unroll
        for (int j = 0; j < 8; j++) op[lane + 32*j] = v[j]*inv;
    }
}

// ---------------------------------------------------------------------------
// 5) Output head + pooling
// ---------------------------------------------------------------------------
__global__ void final_k(const float* __restrict__ S,
                        const float* __restrict__ Wout, const float* __restrict__ bout,
                        const float* __restrict__ Watt, const float* __restrict__ batt){
    __shared__ float wt[PP*HH];
    __shared__ float wa[HH];
    __shared__ float red[8][PP];
    int b = blockIdx.x, seg = blockIdx.y;
    int tid = threadIdx.x, lane = tid & 31, w = tid >> 5;

    for (int i = tid; i < PP*HH; i += 256){
        int d = i / PP, p = i - d*PP;
        wt[p*HH + d] = Wout[i];
    }
    if (tid < HH) wa[tid] = Watt[tid];
    __syncthreads();

    float accp = 0.f;
    float ba = batt[0];
    for (int t = 0; t < 16; t++){
        int n = seg*128 + w*16 + t;
        const float* sp = S + (size_t)(b*NN + n)*HH;
        float s[8], att = 0.f, y[PP];
        #pragma unroll
        for (int p = 0; p < PP; p++) y[p] = 0.f;
        #pragma unroll
        for (int j = 0; j < 8; j++){
            s[j] = sp[lane + 32*j];
            att += s[j]*wa[lane + 32*j];
        }
        #pragma unroll
        for (int p = 0; p < PP; p++)
            #pragma unroll
            for (int j = 0; j < 8; j++) y[p] += s[j]*wt[p*HH + lane + 32*j];
        #pragma unroll
        for (int off = 16; off; off >>= 1){
            att += __shfl_xor_sync(0xffffffffu, att, off);
            #pragma unroll
            for (int p = 0; p < PP; p++) y[p] += __shfl_xor_sync(0xffffffffu, y[p], off);
        }
        float a = 1.0f/(1.0f + expf(-(att + ba)));
        if (lane < PP) accp += a * (y[lane] + bout[lane]);
    }
    if (lane < PP) red[w][lane] = accp;
    __syncthreads();
    if (tid < PP){
        float sum = 0.f;
        #pragma unroll
        for (int w2 = 0; w2 < 8; w2++) sum += red[w2][tid];
        g_pool[(b*8 + seg)*PP + tid] = sum;
    }
}

__global__ void reduce_k(float* __restrict__ out){
    int i = threadIdx.x;
    if (i < BB*PP){
        int b = i / PP, p = i - b*PP;
        float s = 0.f;
        #pragma unroll
        for (int seg = 0; seg < 8; seg++) s += g_pool[(b*8 + seg)*PP + p];
        out[i] = s * (1.0f/NN);
    }
}

// ---------------------------------------------------------------------------
extern "C" void kernel_launch(void* const* d_in, const int* in_sizes, int n_in,
                              void* d_out, int out_size){
    (void)in_sizes; (void)n_in; (void)out_size;
    const int*   nf   = (const int*)  d_in[0];
    const int*   nn   = (const int*)  d_in[1];
    const float* mask = (const float*)d_in[2];
    const float* emb  = (const float*)d_in[3];
    const float* W0   = (const float*)d_in[4];
    const float* b0   = (const float*)d_in[5];
    const float* W1   = (const float*)d_in[6];
    const float* b1   = (const float*)d_in[7];
    const float* Wout = (const float*)d_in[8];
    const float* bout = (const float*)d_in[9];
    const float* Watt = (const float*)d_in[10];
    const float* batt = (const float*)d_in[11];
    float* out = (float*)d_out;

    float *state; __nv_bfloat16 *mhi, *mlo;
    cudaGetSymbolAddress((void**)&state, g_state);
    cudaGetSymbolAddress((void**)&mhi,   g_msg_hi);
    cudaGetSymbolAddress((void**)&mlo,   g_msg_lo);

    cudaFuncSetAttribute(agg_k,      cudaFuncAttributeMaxDynamicSharedMemorySize, 131072);
    cudaFuncSetAttribute(gemm_mma_k, cudaFuncAttributeMaxDynamicSharedMemorySize, GEMM_SMEM);

    embed_k<<<BB*NN*D0/256, 256>>>(nf, emb);

    // Layer 0  (Kd = 512)
    agg_k<<<dim3(BB, D0/32), 256, 131072>>>(state, nn, mask, D0, EE*D0);
    convw_k<<<(EE*D0*HH + 255)/256, 256>>>(W0, EE*D0);
    gemm_mma_k<<<BB*NN/128, 256, GEMM_SMEM>>>(mhi, mlo, EE*D0, b0, state);

    // Layer 1  (Kd = 1024)
    agg_k<<<dim3(BB, HH/32), 256, 131072>>>(state, nn, mask, HH, EE*HH);
    convw_k<<<(EE*HH*HH + 255)/256, 256>>>(W1, EE*HH);
    gemm_mma_k<<<BB*NN/128, 256, GEMM_SMEM>>>(mhi, mlo, EE*HH, b1, state);

    // Output head + pooling
    final_k<<<dim3(BB, 8), 256>>>(state, Wout, bout, Watt, batt);
    reduce_k<<<1, 192>>>(out);
}

// round 4
// speedup vs baseline: 1.7393x; 1.2410x over previous
#include <cuda_runtime.h>
#include <cuda_bf16.h>
#include <math.h>
#include <stdint.h>

#define BB 16
#define NN 1024
#define KK 16
#define EE 4
#define D0 128
#define HH 256
#define PP 10
#define EPSF 1.1920928955078125e-07f

#define NCH1 16            // layer1 K chunks (1024/64); layer0 uses 8
#define MTILES 128         // BB*NN/128

// ---------------- device scratch (allocation-free rule) --------------------
// A tiled: [mtile][ch][row 0..127][64 bf16, swizzled 128B rows]  (16KB per tile-chunk)
__device__ __nv_bfloat16 g_Ahi[MTILES*NCH1*128*64];
__device__ __nv_bfloat16 g_Alo[MTILES*NCH1*128*64];
// B tiled: [ch][n 0..255][64 bf16, swizzled]                      (32KB per chunk)
__device__ __nv_bfloat16 g_Bhi[NCH1*256*64];
__device__ __nv_bfloat16 g_Blo[NCH1*256*64];
__device__ float g_state[BB*NN*HH];
__device__ float g_pool[BB*8*PP];

// ---------------- PTX helpers ----------------------------------------------
__device__ __forceinline__ uint32_t smem_u32(const void* p){
    uint32_t a; asm("{ .reg .u64 t; cvta.to.shared.u64 t, %1; cvt.u32.u64 %0, t; }" : "=r"(a) : "l"(p));
    return a;
}
#define MBAR_INIT(mb, c)  asm volatile("mbarrier.init.shared.b64 [%0], %1;" :: "r"((uint32_t)(mb)), "r"((uint32_t)(c)) : "memory")
#define MBAR_EXPECT(mb, tx) asm volatile("mbarrier.arrive.expect_tx.shared.b64 _, [%0], %1;" :: "r"((uint32_t)(mb)), "r"((uint32_t)(tx)) : "memory")
#define MBAR_WAIT(mb, ph) do { \
    uint32_t _m = (uint32_t)(mb), _p = (uint32_t)(ph), _d; \
    asm volatile("{\n\t.reg .pred p;\n\tmbarrier.try_wait.parity.acquire.cta.shared::cta.b64 p, [%1], %2;\n\tselp.b32 %0, 1, 0, p;\n\t}" \
        : "=r"(_d) : "r"(_m), "r"(_p) : "memory"); \
    if (!_d) { \
        asm volatile("{\n\t.reg .pred P1;\n\tWL_%=:\n\tmbarrier.try_wait.parity.acquire.cta.shared::cta.b64 P1, [%0], %1, 0x989680;\n\t@P1 bra.uni WD_%=;\n\tbra.uni WL_%=;\n\tWD_%=:\n\t}" \
            :: "r"(_m), "r"(_p) : "memory"); \
    } } while(0)
#define BULK_G2S(dst, src, bytes, mb) \
    asm volatile("cp.async.bulk.shared::cluster.global.mbarrier::complete_tx::bytes [%0], [%1], %2, [%3];" \
        :: "r"((uint32_t)(dst)), "l"(src), "r"((uint32_t)(bytes)), "r"((uint32_t)(mb)) : "memory")

#define LDMX4(r, a) \
    asm volatile("ldmatrix.sync.aligned.m8n8.x4.shared.b16 {%0,%1,%2,%3}, [%4];" \
        : "=r"((r)[0]), "=r"((r)[1]), "=r"((r)[2]), "=r"((r)[3]) : "r"(a))

__device__ __forceinline__ void mma16816(float* c, const uint32_t* a, uint32_t b0, uint32_t b1){
    asm volatile("mma.sync.aligned.m16n8k16.row.col.f32.bf16.bf16.f32 "
        "{%0,%1,%2,%3}, {%4,%5,%6,%7}, {%8,%9}, {%0,%1,%2,%3};"
        : "+f"(c[0]), "+f"(c[1]), "+f"(c[2]), "+f"(c[3])
        : "r"(a[0]), "r"(a[1]), "r"(a[2]), "r"(a[3]), "r"(b0), "r"(b1));
}

// swizzled byte offset inside a 128B-row tile: row-major, 16B chunk xor (row&7)
__device__ __forceinline__ uint32_t tswz(int row, int g){   // g = 16B chunk index 0..7
    return (uint32_t)(row*128 + (((g ^ (row & 7))) << 4));
}

// ---------------------------------------------------------------------------
// 1) Aggregation (embed fused for layer0). Output: tiled/swizzled bf16 hi/lo A.
// ---------------------------------------------------------------------------
__global__ __launch_bounds__(512) void agg_k(const float* __restrict__ Sin,
        const int* __restrict__ nf, const float* __restrict__ emb,
        const int* __restrict__ nn_idx, const float* __restrict__ mask,
        int D, int nch, int useEmb, int nsplit_shift){
    extern __shared__ float sbuf[];                 // [1024][32]
    int b  = blockIdx.x;
    int d0 = blockIdx.y * 32;
    int tid = threadIdx.x, lane = tid & 31, w = tid >> 5;

    if (useEmb){
        const int* nfb = nf + b*NN;
        for (int i = tid; i < NN*32; i += 512){
            int row = i >> 5, c = i & 31;
            sbuf[i] = emb[nfb[row]*D0 + d0 + c];
        }
    } else {
        const float* Sb = Sin + (size_t)b*NN*HH;
        for (int i = tid; i < NN*32; i += 512){
            int row = i >> 5, c = i & 31;
            sbuf[i] = Sb[(size_t)row*HH + d0 + c];
        }
    }
    __syncthreads();

    int nPer  = NN >> nsplit_shift;
    int nbase = blockIdx.z * nPer;
    char* Ah = (char*)g_Ahi;
    char* Al = (char*)g_Alo;

    for (int n = nbase + w; n < nbase + nPer; n += 16){
        const int* ip = nn_idx + ((size_t)(b*NN + n))*(KK*EE);
        int i0 = ip[lane] << 5;          // premultiplied row offset
        int i1 = ip[32 + lane] << 5;
        float m = mask[b*NN + n] * (1.0f/KK);
        int mtile = b*8 + (n >> 7);
        int mrow  = n & 127;
        #pragma unroll
        for (int e = 0; e < EE; e++){
            float acc = 0.f;
            #pragma unroll
            for (int k = 0; k < KK; k++){
                int kk = k*EE + e;
                int off = (kk < 32) ? __shfl_sync(0xffffffffu, i0, kk)
                                    : __shfl_sync(0xffffffffu, i1, kk - 32);
                acc += sbuf[off + lane];
            }
            float v = acc * m;
            __nv_bfloat16 h = __float2bfloat16(v);
            __nv_bfloat16 l = __float2bfloat16(v - __bfloat162float(h));
            int kg = e*D + d0 + lane;
            int ch = kg >> 6, kin = kg & 63;
            size_t byt = (((size_t)(mtile*nch + ch)*128 + mrow) << 7)
                       + tswz(0, 0)*0 + ((((kin>>3) ^ (mrow & 7))) << 4) + (kin & 7)*2;
            *(__nv_bfloat16*)(Ah + byt) = h;
            *(__nv_bfloat16*)(Al + byt) = l;
        }
    }
}

// ---------------------------------------------------------------------------
// 2) Weight convert: W[k][n] -> tiled/swizzled Bt[ch][n][kin] hi/lo
// ---------------------------------------------------------------------------
__global__ void convw_k(const float* __restrict__ W, int Kd){
    int i = blockIdx.x*256 + threadIdx.x;
    if (i < Kd*HH){
        int k = i >> 8, n = i & (HH-1);
        float v = W[(size_t)k*HH + n];
        __nv_bfloat16 h = __float2bfloat16(v);
        __nv_bfloat16 l = __float2bfloat16(v - __bfloat162float(h));
        int ch = k >> 6, kin = k & 63;
        size_t byt = (((size_t)(ch*256 + n)) << 7) + ((((kin>>3) ^ (n & 7))) << 4) + (kin & 7)*2;
        *(__nv_bfloat16*)((char*)g_Bhi + byt) = h;
        *(__nv_bfloat16*)((char*)g_Blo + byt) = l;
    }
}

// ---------------------------------------------------------------------------
// 3) GEMM via mma.sync, operands fetched with cp.async.bulk (4 ops/stage),
//    3-term compensated bf16, fused bias+ReLU+L2-norm epilogue.
//    CTA 128x256, 16 warps (warp tile 64x32), K-chunk 64, 2 stages.
//    Stage: Ahi 16K | Alo 16K | Bhi 32K | Blo 32K = 96KB.
// ---------------------------------------------------------------------------
#define STG 98304
#define GEMM_SMEM (2*STG + 64)
#define EPI_STR 258

__global__ __launch_bounds__(512, 1) void gemm_bulk_k(
        int nch, const float* __restrict__ bias, float* __restrict__ S){
    extern __shared__ char smx[];
    uint32_t sb0 = smem_u32(smx);
    uint32_t mb  = sb0 + 2*STG;
    int tid = threadIdx.x, lane = tid & 31, w = tid >> 5;
    int wm = w >> 3, wn = w & 7;
    int mtile = blockIdx.x;

    if (tid == 0){ MBAR_INIT(mb, 1); MBAR_INIT(mb + 8, 1); }
    __syncthreads();

    float c[4][4][4];
    #pragma unroll
    for (int mi = 0; mi < 4; mi++)
        #pragma unroll
        for (int nj = 0; nj < 4; nj++)
            #pragma unroll
            for (int q = 0; q < 4; q++) c[mi][nj][q] = 0.f;

    const char* Ah = (const char*)g_Ahi;
    const char* Al = (const char*)g_Alo;
    const char* Bh = (const char*)g_Bhi;
    const char* Bl = (const char*)g_Blo;

    auto issue = [&](int ch){
        int st = ch & 1;
        uint32_t d = sb0 + st*STG;
        uint32_t m = mb + st*8;
        MBAR_EXPECT(m, STG);
        size_t at = ((size_t)(mtile*nch + ch)) << 14;    // *16384
        size_t bt = ((size_t)ch) << 15;                   // *32768
        BULK_G2S(d,         Ah + at, 16384, m);
        BULK_G2S(d + 16384, Al + at, 16384, m);
        BULK_G2S(d + 32768, Bh + bt, 32768, m);
        BULK_G2S(d + 65536, Bl + bt, 32768, m);
    };

    if (tid == 0){ issue(0); issue(1); }
    int ph0 = 0, ph1 = 0;

    for (int ch = 0; ch < nch; ch++){
        int st = ch & 1;
        if (st == 0){ MBAR_WAIT(mb,     ph0); ph0 ^= 1; }
        else        { MBAR_WAIT(mb + 8, ph1); ph1 ^= 1; }

        uint32_t sbase = sb0 + st*STG;
        #pragma unroll
        for (int pass = 0; pass < 3; pass++){
            uint32_t ab = sbase + (pass == 2 ? 16384 : 0);
            uint32_t bb = sbase + 32768 + (pass == 1 ? 32768 : 0);
            #pragma unroll
            for (int s = 0; s < 4; s++){
                int lrow = lane & 15;
                int g = 2*s + (lane >> 4);
                uint32_t a[4][4], bq[2][4];
                #pragma unroll
                for (int mi = 0; mi < 4; mi++){
                    int row = wm*64 + mi*16 + lrow;
                    LDMX4(a[mi], ab + tswz(row, g));
                }
                #pragma unroll
                for (int nj = 0; nj < 2; nj++){
                    int row = wn*32 + nj*16 + lrow;
                    LDMX4(bq[nj], bb + tswz(row, g));
                }
                #pragma unroll
                for (int mi = 0; mi < 4; mi++)
                    #pragma unroll
                    for (int nj = 0; nj < 2; nj++){
                        mma16816(c[mi][2*nj+0], a[mi], bq[nj][0], bq[nj][2]);
                        mma16816(c[mi][2*nj+1], a[mi], bq[nj][1], bq[nj][3]);
                    }
            }
        }
        __syncthreads();                      // stage fully consumed
        if (tid == 0 && ch + 2 < nch) issue(ch + 2);
    }
    __syncthreads();

    // --- epilogue: bias + relu into smem, fused row L2-norm ---
    float* sbuf = (float*)smx;
    int qr = lane >> 2, qc = (lane & 3)*2;
    #pragma unroll
    for (int mi = 0; mi < 4; mi++){
        int r0 = wm*64 + mi*16 + qr;
        #pragma unroll
        for (int nj = 0; nj < 4; nj++){
            int col = wn*32 + nj*8 + qc;
            float b0 = bias[col], b1 = bias[col+1];
            *(float2*)&sbuf[(size_t)r0*EPI_STR + col] =
                make_float2(fmaxf(c[mi][nj][0] + b0, 0.f), fmaxf(c[mi][nj][1] + b1, 0.f));
            *(float2*)&sbuf[(size_t)(r0+8)*EPI_STR + col] =
                make_float2(fmaxf(c[mi][nj][2] + b0, 0.f), fmaxf(c[mi][nj][3] + b1, 0.f));
        }
    }
    __syncthreads();

    int m0 = mtile*128;
    #pragma unroll
    for (int r = 0; r < 8; r++){
        int row = w*8 + r;
        const float* rp = &sbuf[(size_t)row*EPI_STR];
        float v[8], ss = 0.f;
        #pragma unroll
        for (int j = 0; j < 8; j++){ v[j] = rp[lane + 32*j]; ss += v[j]*v[j]; }
        #pragma unroll
        for (int off = 16; off; off >>= 1) ss += __shfl_xor_sync(0xffffffffu, ss, off);
        float inv = 1.0f/(sqrtf(ss) + EPSF);
        float* op = S + (size_t)(m0 + row)*HH;
        #pragma unroll
        for (int j = 0; j < 8; j++) op[lane + 32*j] = v[j]*inv;
    }
}

// ---------------------------------------------------------------------------
// 4) Output head + pooling
// ---------------------------------------------------------------------------
__global__ void final_k(const float* __restrict__ S,
                        const float* __restrict__ Wout, const float* __restrict__ bout,
                        const float* __restrict__ Watt, const float* __restrict__ batt){
    __shared__ float wt[PP*HH];
    __shared__ float wa[HH];
    __shared__ float red[8][PP];
    int b = blockIdx.x, seg = blockIdx.y;
    int tid = threadIdx.x, lane = tid & 31, w = tid >> 5;

    for (int i = tid; i < PP*HH; i += 256){
        int d = i / PP, p = i - d*PP;
        wt[p*HH + d] = Wout[i];
    }
    if (tid < HH) wa[tid] = Watt[tid];
    __syncthreads();

    float accp = 0.f;
    float ba = batt[0];
    for (int t = 0; t < 16; t++){
        int n = seg*128 + w*16 + t;
        const float* sp = S + (size_t)(b*NN + n)*HH;
        float s[8], att = 0.f, y[PP];
        #pragma unroll
        for (int p = 0; p < PP; p++) y[p] = 0.f;
        #pragma unroll
        for (int j = 0; j < 8; j++){
            s[j] = sp[lane + 32*j];
            att += s[j]*wa[lane + 32*j];
        }
        #pragma unroll
        for (int p = 0; p < PP; p++)
            #pragma unroll
            for (int j = 0; j < 8; j++) y[p] += s[j]*wt[p*HH + lane + 32*j];
        #pragma unroll
        for (int off = 16; off; off >>= 1){
            att += __shfl_xor_sync(0xffffffffu, att, off);
            #pragma unroll
            for (int p = 0; p < PP; p++) y[p] += __shfl_xor_sync(0xffffffffu, y[p], off);
        }
        float a = 1.0f/(1.0f + expf(-(att + ba)));
        if (lane < PP) accp += a * (y[lane] + bout[lane]);
    }
    if (lane < PP) red[w][lane] = accp;
    __syncthreads();
    if (tid < PP){
        float sum = 0.f;
        #pragma unroll
        for (int w2 = 0; w2 < 8; w2++) sum += red[w2][tid];
        g_pool[(b*8 + seg)*PP + tid] = sum;
    }
}

__global__ void reduce_k(float* __restrict__ out){
    int i = threadIdx.x;
    if (i < BB*PP){
        int b = i / PP, p = i - b*PP;
        float s = 0.f;
        #pragma unroll
        for (int seg = 0; seg < 8; seg++) s += g_pool[(b*8 + seg)*PP + p];
        out[i] = s * (1.0f/NN);
    }
}

// ---------------------------------------------------------------------------
extern "C" void kernel_launch(void* const* d_in, const int* in_sizes, int n_in,
                              void* d_out, int out_size){
    (void)in_sizes; (void)n_in; (void)out_size;
    const int*   nf   = (const int*)  d_in[0];
    const int*   nn   = (const int*)  d_in[1];
    const float* mask = (const float*)d_in[2];
    const float* emb  = (const float*)d_in[3];
    const float* W0   = (const float*)d_in[4];
    const float* b0   = (const float*)d_in[5];
    const float* W1   = (const float*)d_in[6];
    const float* b1   = (const float*)d_in[7];
    const float* Wout = (const float*)d_in[8];
    const float* bout = (const float*)d_in[9];
    const float* Watt = (const float*)d_in[10];
    const float* batt = (const float*)d_in[11];
    float* out = (float*)d_out;

    float *state;
    cudaGetSymbolAddress((void**)&state, g_state);

    cudaFuncSetAttribute(agg_k,       cudaFuncAttributeMaxDynamicSharedMemorySize, 131072);
    cudaFuncSetAttribute(gemm_bulk_k, cudaFuncAttributeMaxDynamicSharedMemorySize, GEMM_SMEM);

    // Layer 0 (Kd=512, nch=8): embed fused into agg (useEmb=1), z-split 2
    convw_k<<<(512*HH + 255)/256, 256>>>(W0, 512);
    agg_k<<<dim3(BB, D0/32, 2), 512, 131072>>>(state, nf, emb, nn, mask, D0, 8, 1, 1);
    gemm_bulk_k<<<MTILES, 512, GEMM_SMEM>>>(8, b0, state);

    // Layer 1 (Kd=1024, nch=16)
    convw_k<<<(1024*HH + 255)/256, 256>>>(W1, 1024);
    agg_k<<<dim3(BB, HH/32, 1), 512, 131072>>>(state, nf, emb, nn, mask, HH, 16, 0, 0);
    gemm_bulk_k<<<MTILES, 512, GEMM_SMEM>>>(16, b1, state);

    // Output head + pooling
    final_k<<<dim3(BB, 8), 256>>>(state, Wout, bout, Watt, batt);
    reduce_k<<<1, 192>>>(out);
}

// round 5
// speedup vs baseline: 2.2676x; 1.3037x over previous
#include <cuda_runtime.h>
#include <cuda_fp16.h>
#include <math.h>
#include <stdint.h>

#define BB 16
#define NN 1024
#define KK 16
#define EE 4
#define D0 128
#define HH 256
#define PP 10
#define EPSF 1.1920928955078125e-07f

#define NCH1 16            // layer1 K chunks (1024/64); layer0 uses 8
#define MTILES 128         // BB*NN/128

// ---------------- device scratch (allocation-free rule) --------------------
// A tiled fp16: [mtile][ch][row 0..127][64 f16, swizzled 128B rows] (16KB/tile-chunk)
__device__ __half g_Af[MTILES*NCH1*128*64];
// B tiled fp16 hi/lo per layer: [ch][n 0..255][64 f16, swizzled] (32KB/chunk)
__device__ __half g_Bh0[8*256*64];
__device__ __half g_Bl0[8*256*64];
__device__ __half g_Bh1[16*256*64];
__device__ __half g_Bl1[16*256*64];
__device__ float g_state[BB*NN*HH];
__device__ float g_pool[BB*8*PP];

// ---------------- PTX helpers ----------------------------------------------
__device__ __forceinline__ uint32_t smem_u32(const void* p){
    uint32_t a; asm("{ .reg .u64 t; cvta.to.shared.u64 t, %1; cvt.u32.u64 %0, t; }" : "=r"(a) : "l"(p));
    return a;
}
#define MBAR_INIT(mb, c)  asm volatile("mbarrier.init.shared.b64 [%0], %1;" :: "r"((uint32_t)(mb)), "r"((uint32_t)(c)) : "memory")
#define MBAR_EXPECT(mb, tx) asm volatile("mbarrier.arrive.expect_tx.shared.b64 _, [%0], %1;" :: "r"((uint32_t)(mb)), "r"((uint32_t)(tx)) : "memory")
#define MBAR_WAIT(mb, ph) do { \
    uint32_t _m = (uint32_t)(mb), _p = (uint32_t)(ph), _d; \
    asm volatile("{\n\t.reg .pred p;\n\tmbarrier.try_wait.parity.acquire.cta.shared::cta.b64 p, [%1], %2;\n\tselp.b32 %0, 1, 0, p;\n\t}" \
        : "=r"(_d) : "r"(_m), "r"(_p) : "memory"); \
    if (!_d) { \
        asm volatile("{\n\t.reg .pred P1;\n\tWL_%=:\n\tmbarrier.try_wait.parity.acquire.cta.shared::cta.b64 P1, [%0], %1, 0x989680;\n\t@P1 bra.uni WD_%=;\n\tbra.uni WL_%=;\n\tWD_%=:\n\t}" \
            :: "r"(_m), "r"(_p) : "memory"); \
    } } while(0)
#define BULK_G2S(dst, src, bytes, mb) \
    asm volatile("cp.async.bulk.shared::cluster.global.mbarrier::complete_tx::bytes [%0], [%1], %2, [%3];" \
        :: "r"((uint32_t)(dst)), "l"(src), "r"((uint32_t)(bytes)), "r"((uint32_t)(mb)) : "memory")

#define LDMX4(r, a) \
    asm volatile("ldmatrix.sync.aligned.m8n8.x4.shared.b16 {%0,%1,%2,%3}, [%4];" \
        : "=r"((r)[0]), "=r"((r)[1]), "=r"((r)[2]), "=r"((r)[3]) : "r"(a))

__device__ __forceinline__ void mma16816(float* c, const uint32_t* a, uint32_t b0, uint32_t b1){
    asm volatile("mma.sync.aligned.m16n8k16.row.col.f32.f16.f16.f32 "
        "{%0,%1,%2,%3}, {%4,%5,%6,%7}, {%8,%9}, {%0,%1,%2,%3};"
        : "+f"(c[0]), "+f"(c[1]), "+f"(c[2]), "+f"(c[3])
        : "r"(a[0]), "r"(a[1]), "r"(a[2]), "r"(a[3]), "r"(b0), "r"(b1));
}

// swizzled byte offset inside a 128B-row tile: 16B chunk g xor (row&7)
__device__ __forceinline__ uint32_t tswz(int row, int g){
    return (uint32_t)(row*128 + (((g ^ (row & 7))) << 4));
}

// ---------------------------------------------------------------------------
// 1) Aggregation (embed fused for layer0): SMEM-staged gather, SHFL-free.
//    Per node: 16 uniform LDG.128 (int4 = 4 edge-type indices for k) +
//    64 LDS + 64 FADD. Output: tiled/swizzled fp16 A.
// ---------------------------------------------------------------------------
__global__ __launch_bounds__(512) void agg_k(const float* __restrict__ Sin,
        const int* __restrict__ nf, const float* __restrict__ emb,
        const int* __restrict__ nn_idx, const float* __restrict__ mask,
        int D, int nch, int useEmb, int nsplit_shift){
    extern __shared__ float sbuf[];                 // [1024][32]
    int b  = blockIdx.x;
    int d0 = blockIdx.y * 32;
    int tid = threadIdx.x, lane = tid & 31, w = tid >> 5;

    if (useEmb){
        const int* nfb = nf + b*NN;
        for (int i = tid; i < NN*32; i += 512){
            int row = i >> 5, c = i & 31;
            sbuf[i] = emb[nfb[row]*D0 + d0 + c];
        }
    } else {
        const float* Sb = Sin + (size_t)b*NN*HH;
        for (int i = tid; i < NN*32; i += 512){
            int row = i >> 5, c = i & 31;
            sbuf[i] = Sb[(size_t)row*HH + d0 + c];
        }
    }
    __syncthreads();

    int nPer  = NN >> nsplit_shift;
    int nbase = blockIdx.z * nPer;
    char* Ag = (char*)g_Af;

    for (int n = nbase + w; n < nbase + nPer; n += 16){
        const int4* ip4 = (const int4*)(nn_idx + ((size_t)(b*NN + n))*(KK*EE));
        float a0 = 0.f, a1 = 0.f, a2 = 0.f, a3 = 0.f;
        #pragma unroll
        for (int g = 0; g < KK; g++){
            int4 q = __ldg(&ip4[g]);      // uniform across warp: k=g, e=0..3
            a0 += sbuf[q.x*32 + lane];
            a1 += sbuf[q.y*32 + lane];
            a2 += sbuf[q.z*32 + lane];
            a3 += sbuf[q.w*32 + lane];
        }
        float m = mask[b*NN + n] * (1.0f/KK);
        int mtile = b*8 + (n >> 7);
        int mrow  = n & 127;
        size_t tbase = ((size_t)mtile*nch) << 14;   // *16384 bytes
        float av[4] = {a0, a1, a2, a3};
        #pragma unroll
        for (int e = 0; e < EE; e++){
            int kg = e*D + d0 + lane;
            int ch = kg >> 6, kin = kg & 63;
            size_t byt = tbase + (((size_t)ch*128 + mrow) << 7)
                       + ((((kin>>3) ^ (mrow & 7))) << 4) + ((kin & 7) << 1);
            *(__half*)(Ag + byt) = __float2half(av[e] * m);
        }
    }
}

// ---------------------------------------------------------------------------
// 2) Weight convert (both layers, one launch): W[k][n] -> tiled/swizzled
//    fp16 hi/lo. Thread = one 16B output granule (8 k-values of one column).
// ---------------------------------------------------------------------------
__global__ void convw_k(const float* __restrict__ W0, const float* __restrict__ W1){
    int t = blockIdx.x*256 + threadIdx.x;           // 0 .. 49151
    const float* W; __half *Bh, *Bl; int g;
    if (t < 16384){ W = W0; Bh = g_Bh0; Bl = g_Bl0; g = t; }
    else          { W = W1; Bh = g_Bh1; Bl = g_Bl1; g = t - 16384; }
    int n  = g & 255;
    int kq = g >> 8;            // granule row: k = kq*8 + j
    __half hv[8], lv[8];
    #pragma unroll
    for (int j = 0; j < 8; j++){
        float v = W[(size_t)(kq*8 + j)*HH + n];
        __half h = __float2half(v);
        hv[j] = h;
        lv[j] = __float2half(v - __half2float(h));
    }
    int ch = kq >> 3;
    size_t byt = (((size_t)(ch*256 + n)) << 7) + ((((kq & 7) ^ (n & 7))) << 4);
    *(uint4*)((char*)Bh + byt) = *(uint4*)hv;
    *(uint4*)((char*)Bl + byt) = *(uint4*)lv;
}

// ---------------------------------------------------------------------------
// 3) GEMM: 2-pass compensated fp16 (A single, B = Bh + Bl), cp.async.bulk
//    staged operands, fused bias+ReLU+L2-norm epilogue.
//    CTA 128x256, 16 warps (warp tile 64x32), K-chunk 64, 2 stages.
//    Stage: A 16K | Bh 32K | Bl 32K = 80KB.
// ---------------------------------------------------------------------------
#define STG 81920
#define GEMM_SMEM (2*STG + 64)
#define EPI_STR 258

__global__ __launch_bounds__(512, 1) void gemm2_k(
        const __half* __restrict__ Agl, const __half* __restrict__ Bhg,
        const __half* __restrict__ Blg, int nch,
        const float* __restrict__ bias, float* __restrict__ S){
    extern __shared__ char smx[];
    uint32_t sb0 = smem_u32(smx);
    uint32_t mb  = sb0 + 2*STG;
    int tid = threadIdx.x, lane = tid & 31, w = tid >> 5;
    int wm = w >> 3, wn = w & 7;
    int mtile = blockIdx.x;

    if (tid == 0){ MBAR_INIT(mb, 1); MBAR_INIT(mb + 8, 1); }
    __syncthreads();

    float c[4][4][4];
    #pragma unroll
    for (int mi = 0; mi < 4; mi++)
        #pragma unroll
        for (int nj = 0; nj < 4; nj++)
            #pragma unroll
            for (int q = 0; q < 4; q++) c[mi][nj][q] = 0.f;

    auto issue = [&](int ch){
        int st = ch & 1;
        uint32_t d = sb0 + st*STG;
        uint32_t m = mb + st*8;
        MBAR_EXPECT(m, STG);
        BULK_G2S(d,         (const char*)Agl + (((size_t)(mtile*nch + ch)) << 14), 16384, m);
        BULK_G2S(d + 16384, (const char*)Bhg + (((size_t)ch) << 15),               32768, m);
        BULK_G2S(d + 49152, (const char*)Blg + (((size_t)ch) << 15),               32768, m);
    };

    if (tid == 0){ issue(0); issue(1); }
    int ph0 = 0, ph1 = 0;

    for (int ch = 0; ch < nch; ch++){
        int st = ch & 1;
        if (st == 0){ MBAR_WAIT(mb,     ph0); ph0 ^= 1; }
        else        { MBAR_WAIT(mb + 8, ph1); ph1 ^= 1; }

        uint32_t ab = sb0 + st*STG;
        uint32_t bh = ab + 16384;
        uint32_t bl = ab + 49152;
        #pragma unroll
        for (int s = 0; s < 4; s++){
            int lrow = lane & 15;
            int g = 2*s + (lane >> 4);
            uint32_t a[4][4], bq[2][4], bp[2][4];
            #pragma unroll
            for (int mi = 0; mi < 4; mi++){
                int row = wm*64 + mi*16 + lrow;
                LDMX4(a[mi], ab + tswz(row, g));
            }
            #pragma unroll
            for (int nj = 0; nj < 2; nj++){
                int row = wn*32 + nj*16 + lrow;
                LDMX4(bq[nj], bh + tswz(row, g));
                LDMX4(bp[nj], bl + tswz(row, g));
            }
            #pragma unroll
            for (int mi = 0; mi < 4; mi++)
                #pragma unroll
                for (int nj = 0; nj < 2; nj++){
                    mma16816(c[mi][2*nj+0], a[mi], bq[nj][0], bq[nj][2]);
                    mma16816(c[mi][2*nj+1], a[mi], bq[nj][1], bq[nj][3]);
                    mma16816(c[mi][2*nj+0], a[mi], bp[nj][0], bp[nj][2]);
                    mma16816(c[mi][2*nj+1], a[mi], bp[nj][1], bp[nj][3]);
                }
        }
        __syncthreads();                      // stage fully consumed
        if (tid == 0 && ch + 2 < nch) issue(ch + 2);
    }
    __syncthreads();

    // --- epilogue: bias + relu into smem, fused row L2-norm ---
    float* sbuf = (float*)smx;
    int qr = lane >> 2, qc = (lane & 3)*2;
    #pragma unroll
    for (int mi = 0; mi < 4; mi++){
        int r0 = wm*64 + mi*16 + qr;
        #pragma unroll
        for (int nj = 0; nj < 4; nj++){
            int col = wn*32 + nj*8 + qc;
            float b0 = bias[col], b1 = bias[col+1];
            *(float2*)&sbuf[(size_t)r0*EPI_STR + col] =
                make_float2(fmaxf(c[mi][nj][0] + b0, 0.f), fmaxf(c[mi][nj][1] + b1, 0.f));
            *(float2*)&sbuf[(size_t)(r0+8)*EPI_STR + col] =
                make_float2(fmaxf(c[mi][nj][2] + b0, 0.f), fmaxf(c[mi][nj][3] + b1, 0.f));
        }
    }
    __syncthreads();

    int m0 = mtile*128;
    #pragma unroll
    for (int r = 0; r < 8; r++){
        int row = w*8 + r;
        const float* rp = &sbuf[(size_t)row*EPI_STR];
        float v[8], ss = 0.f;
        #pragma unroll
        for (int j = 0; j < 8; j++){ v[j] = rp[lane + 32*j]; ss += v[j]*v[j]; }
        #pragma unroll
        for (int off = 16; off; off >>= 1) ss += __shfl_xor_sync(0xffffffffu, ss, off);
        float inv = 1.0f/(sqrtf(ss) + EPSF);
        float* op = S + (size_t)(m0 + row)*HH;
        #pragma unroll
        for (int j = 0; j < 8; j++) op[lane + 32*j] = v[j]*inv;
    }
}

// ---------------------------------------------------------------------------
// 4) Output head + pooling
// ---------------------------------------------------------------------------
__global__ void final_k(const float* __restrict__ S,
                        const float* __restrict__ Wout, const float* __restrict__ bout,
                        const float* __restrict__ Watt, const float* __restrict__ batt){
    __shared__ float wt[PP*HH];
    __shared__ float wa[HH];
    __shared__ float red[8][PP];
    int b = blockIdx.x, seg = blockIdx.y;
    int tid = threadIdx.x, lane = tid & 31, w = tid >> 5;

    for (int i = tid; i < PP*HH; i += 256){
        int d = i / PP, p = i - d*PP;
        wt[p*HH + d] = Wout[i];
    }
    if (tid < HH) wa[tid] = Watt[tid];
    __syncthreads();

    float accp = 0.f;
    float ba = batt[0];
    for (int t = 0; t < 16; t++){
        int n = seg*128 + w*16 + t;
        const float* sp = S + (size_t)(b*NN + n)*HH;
        float s[8], att = 0.f, y[PP];
        #pragma unroll
        for (int p = 0; p < PP; p++) y[p] = 0.f;
        #pragma unroll
        for (int j = 0; j < 8; j++){
            s[j] = sp[lane + 32*j];
            att += s[j]*wa[lane + 32*j];
        }
        #pragma unroll
        for (int p = 0; p < PP; p++)
            #pragma unroll
            for (int j = 0; j < 8; j++) y[p] += s[j]*wt[p*HH + lane + 32*j];
        #pragma unroll
        for (int off = 16; off; off >>= 1){
            att += __shfl_xor_sync(0xffffffffu, att, off);
            #pragma unroll
            for (int p = 0; p < PP; p++) y[p] += __shfl_xor_sync(0xffffffffu, y[p], off);
        }
        float a = 1.0f/(1.0f + expf(-(att + ba)));
        if (lane < PP) accp += a * (y[lane] + bout[lane]);
    }
    if (lane < PP) red[w][lane] = accp;
    __syncthreads();
    if (tid < PP){
        float sum = 0.f;
        #pragma unroll
        for (int w2 = 0; w2 < 8; w2++) sum += red[w2][tid];
        g_pool[(b*8 + seg)*PP + tid] = sum;
    }
}

__global__ void reduce_k(float* __restrict__ out){
    int i = threadIdx.x;
    if (i < BB*PP){
        int b = i / PP, p = i - b*PP;
        float s = 0.f;
        #pragma unroll
        for (int seg = 0; seg < 8; seg++) s += g_pool[(b*8 + seg)*PP + p];
        out[i] = s * (1.0f/NN);
    }
}

// ---------------------------------------------------------------------------
extern "C" void kernel_launch(void* const* d_in, const int* in_sizes, int n_in,
                              void* d_out, int out_size){
    (void)in_sizes; (void)n_in; (void)out_size;
    const int*   nf   = (const int*)  d_in[0];
    const int*   nn   = (const int*)  d_in[1];
    const float* mask = (const float*)d_in[2];
    const float* emb  = (const float*)d_in[3];
    const float* W0   = (const float*)d_in[4];
    const float* b0   = (const float*)d_in[5];
    const float* W1   = (const float*)d_in[6];
    const float* b1   = (const float*)d_in[7];
    const float* Wout = (const float*)d_in[8];
    const float* bout = (const float*)d_in[9];
    const float* Watt = (const float*)d_in[10];
    const float* batt = (const float*)d_in[11];
    float* out = (float*)d_out;

    float *state; __half *af, *bh0, *bl0, *bh1, *bl1;
    cudaGetSymbolAddress((void**)&state, g_state);
    cudaGetSymbolAddress((void**)&af,  g_Af);
    cudaGetSymbolAddress((void**)&bh0, g_Bh0);
    cudaGetSymbolAddress((void**)&bl0, g_Bl0);
    cudaGetSymbolAddress((void**)&bh1, g_Bh1);
    cudaGetSymbolAddress((void**)&bl1, g_Bl1);

    cudaFuncSetAttribute(agg_k,   cudaFuncAttributeMaxDynamicSharedMemorySize, 131072);
    cudaFuncSetAttribute(gemm2_k, cudaFuncAttributeMaxDynamicSharedMemorySize, GEMM_SMEM);

    // Weight conversion for both layers (one launch)
    convw_k<<<192, 256>>>(W0, W1);

    // Layer 0 (Kd=512, nch=8): embed fused into agg, z-split 2
    agg_k<<<dim3(BB, D0/32, 2), 512, 131072>>>(state, nf, emb, nn, mask, D0, 8, 1, 1);
    gemm2_k<<<MTILES, 512, GEMM_SMEM>>>(af, bh0, bl0, 8, b0, state);

    // Layer 1 (Kd=1024, nch=16)
    agg_k<<<dim3(BB, HH/32, 1), 512, 131072>>>(state, nf, emb, nn, mask, HH, 16, 0, 0);
    gemm2_k<<<MTILES, 512, GEMM_SMEM>>>(af, bh1, bl1, 16, b1, state);

    // Output head + pooling
    final_k<<<dim3(BB, 8), 256>>>(state, Wout, bout, Watt, batt);
    reduce_k<<<1, 192>>>(out);
}